// round 12
// baseline (speedup 1.0000x reference)
#include <cuda_runtime.h>
#include <cuda_fp16.h>
#include <cstdint>

// ============================================================================
// out[M,N] = x[M,K] @ w_bin[N,K]^T + bias[N]
//   w_bin = (w < mean-std || w > mean+std) ? w : sign(w)   (std: ddof=1)
// Shapes: M=16384, K=4096, N=4096 fp32.
// Engine: fp16 convert + mma.sync.m16n8k16 pipelined GEMM (base sm_103 ISA).
// R12: R11 (128 thr, 64x64 warps, 2 CTAs/SM, frag double-buffer) + BK=64 so
//      the per-kt barrier/LDSM window amortizes over 2048 MMA cyc (was 1024).
//      HMMA.16816-f32 measured rt=8cyc/SMSP -> floor ~1000us GEMM.
// ============================================================================

#define MAXM 16384
#define MAXN 4096
#define MAXK 4096

__device__ __half g_Xh[(size_t)MAXM * MAXK];   // 128 MiB scratch
__device__ __half g_Wb[(size_t)MAXN * MAXK];   // 32 MiB scratch
__device__ double g_part[2048];

// ---------------------------------------------------------------- stats ----
__global__ void stats1_kernel(const float* __restrict__ w, int n) {
    __shared__ double ss[256], sq[256];
    double s = 0.0, q = 0.0;
    for (int i = blockIdx.x * blockDim.x + threadIdx.x; i < n; i += gridDim.x * blockDim.x) {
        double v = (double)w[i];
        s += v; q += v * v;
    }
    ss[threadIdx.x] = s; sq[threadIdx.x] = q;
    __syncthreads();
    for (int o = 128; o > 0; o >>= 1) {
        if (threadIdx.x < o) { ss[threadIdx.x] += ss[threadIdx.x + o]; sq[threadIdx.x] += sq[threadIdx.x + o]; }
        __syncthreads();
    }
    if (threadIdx.x == 0) { g_part[blockIdx.x * 2] = ss[0]; g_part[blockIdx.x * 2 + 1] = sq[0]; }
}

__device__ __forceinline__ float binv(float w, float lo, float hi) {
    if (w < lo || w > hi) return w;
    return (w > 0.f) ? 1.f : ((w < 0.f) ? -1.f : 0.f);
}

// binarize + final threshold reduce fused (each block redundantly reduces the
// 1024 partials — deterministic, a few us total).
__global__ void binarize_kernel(const float* __restrict__ w, int n4, int n) {
    __shared__ double ss[256], sq[256];
    __shared__ float thr[2];
    double s = 0.0, q = 0.0;
    for (int i = threadIdx.x; i < 1024; i += 256) { s += g_part[2 * i]; q += g_part[2 * i + 1]; }
    ss[threadIdx.x] = s; sq[threadIdx.x] = q;
    __syncthreads();
    for (int o = 128; o > 0; o >>= 1) {
        if (threadIdx.x < o) { ss[threadIdx.x] += ss[threadIdx.x + o]; sq[threadIdx.x] += sq[threadIdx.x + o]; }
        __syncthreads();
    }
    if (threadIdx.x == 0) {
        double mean = ss[0] / (double)n;
        double var  = (sq[0] - ss[0] * ss[0] / (double)n) / (double)(n - 1);
        double sd = sqrt(var);
        thr[0] = (float)(mean - sd);
        thr[1] = (float)(mean + sd);
    }
    __syncthreads();
    float lo = thr[0], hi = thr[1];
    const float4* w4 = (const float4*)w;
    __half2* o2 = (__half2*)g_Wb;
    for (int i = blockIdx.x * blockDim.x + threadIdx.x; i < n4; i += gridDim.x * blockDim.x) {
        float4 v = w4[i];
        o2[2 * i]     = __floats2half2_rn(binv(v.x, lo, hi), binv(v.y, lo, hi));
        o2[2 * i + 1] = __floats2half2_rn(binv(v.z, lo, hi), binv(v.w, lo, hi));
    }
}

__global__ void xconv_kernel(const float* __restrict__ x, int n4) {
    const float4* x4 = (const float4*)x;
    __half2* o2 = (__half2*)g_Xh;
    for (int i = blockIdx.x * blockDim.x + threadIdx.x; i < n4; i += gridDim.x * blockDim.x) {
        float4 v = x4[i];
        o2[2 * i]     = __floats2half2_rn(v.x, v.y);
        o2[2 * i + 1] = __floats2half2_rn(v.z, v.w);
    }
}

// ---------------------------------------------------------------- GEMM -----
// CTA tile 128x128, BK=64, 3-stage cp.async, 128 threads (4 warps 2x2),
// warp tile 64x64, fragment double-buffering, 2 CTAs/SM.
// Smem rows 144B: 16B-aligned cp.async dsts, ldmatrix phase-conflict-free.

#define BM 128
#define BN 128
#define BK 64
#define ROWB 144
#define STAGE_A (BM * ROWB)           // 18432
#define STAGE_B (BN * ROWB)           // 18432
#define STAGE   (STAGE_A + STAGE_B)   // 36864
#define NSTG 3
#define GEMM_SMEM (NSTG * STAGE)      // 110592 (x2 CTAs = 221KB/SM)

__device__ __forceinline__ uint32_t smem_u32(const void* p) {
    uint32_t a;
    asm("{ .reg .u64 t; cvta.to.shared.u64 t, %1; cvt.u32.u64 %0, t; }" : "=r"(a) : "l"(p));
    return a;
}
__device__ __forceinline__ void cp16(uint32_t s, const void* g) {
    asm volatile("cp.async.cg.shared.global [%0], [%1], 16;" :: "r"(s), "l"(g));
}
#define CP_COMMIT() asm volatile("cp.async.commit_group;" ::: "memory")
#define CP_WAIT1()  asm volatile("cp.async.wait_group %0;" :: "n"(1) : "memory")

#define LDSM4(r0, r1, r2, r3, addr) \
    asm volatile("ldmatrix.sync.aligned.m8n8.x4.shared.b16 {%0,%1,%2,%3}, [%4];" \
        : "=r"(r0), "=r"(r1), "=r"(r2), "=r"(r3) : "r"(addr))

__device__ __forceinline__ void mma16816(float* d, const uint32_t* a, const uint32_t* b) {
    asm volatile(
        "mma.sync.aligned.m16n8k16.row.col.f32.f16.f16.f32 "
        "{%0,%1,%2,%3}, {%4,%5,%6,%7}, {%8,%9}, {%0,%1,%2,%3};"
        : "+f"(d[0]), "+f"(d[1]), "+f"(d[2]), "+f"(d[3])
        : "r"(a[0]), "r"(a[1]), "r"(a[2]), "r"(a[3]), "r"(b[0]), "r"(b[1]));
}

// One BK=64 stage: A 128x64 fp16 (1024 x 16B chunks), B 128x64 (1024 chunks).
__device__ __forceinline__ void issue_stage(
    uint32_t sb, int stage, const __half* __restrict__ gA,
    const __half* __restrict__ gB, int kt, int tid, int K)
{
    uint32_t sA = sb + stage * STAGE;
    uint32_t sB = sA + STAGE_A;
    const __half* ga = gA + (size_t)kt * BK;
    #pragma unroll
    for (int j = 0; j < 8; j++) {                  // A: 1024 chunks / 128 thr
        int cid = tid + j * 128;
        int r = cid >> 3, c = cid & 7;
        cp16(sA + r * ROWB + c * 16, ga + (size_t)r * K + c * 8);
    }
    const __half* gb = gB + (size_t)kt * BK;
    #pragma unroll
    for (int j = 0; j < 8; j++) {                  // B: 1024 chunks / 128 thr
        int cid = tid + j * 128;
        int r = cid >> 3, c = cid & 7;
        cp16(sB + r * ROWB + c * 16, gb + (size_t)r * K + c * 8);
    }
}

__global__ void __launch_bounds__(128, 2)
gemm_kernel(float* __restrict__ out, const float* __restrict__ bias,
            const __half* __restrict__ A, const __half* __restrict__ B,
            int M, int N, int K)
{
    extern __shared__ char smem[];
    uint32_t sb = smem_u32(smem);

    int tid = threadIdx.x;
    int wid = tid >> 5, L = tid & 31;
    int warpM = wid >> 1, warpN = wid & 1;         // 2(M) x 2(N)

    int NT = N / BN;                               // 32
    int ntile = blockIdx.x % NT;                   // fast N => W stays L2-hot
    int mtile = blockIdx.x / NT;

    const __half* gA = A + (size_t)(mtile * BM) * K;
    const __half* gB = B + (size_t)(ntile * BN) * K;
    int KT = K / BK;                               // 64

    float acc[4][8][4];
    #pragma unroll
    for (int i = 0; i < 4; i++)
        #pragma unroll
        for (int j = 0; j < 8; j++)
            #pragma unroll
            for (int q = 0; q < 4; q++) acc[i][j][q] = 0.f;

    // prologue: fill 2 of 3 stages
    issue_stage(sb, 0, gA, gB, 0, tid, K); CP_COMMIT();
    issue_stage(sb, 1, gA, gB, 1, tid, K); CP_COMMIT();

    // ldmatrix lane offsets (warp 64x64 mapping validated R6/R11)
    int aRow = warpM * 64 + (L & 15);              // + mt*16
    int aCol = (L >> 4) << 3;                      // + ks*16
    int jb = L >> 3;
    int bRowBase = warpN * 64 + ((jb >> 1) << 3) + (L & 7);   // + p*16
    int bCol = (jb & 1) << 3;                      // + ks*16

    uint32_t aF[2][4][4], bF[2][8][2];

    int st = 0;                                    // stage of current kt
    for (int kt = 0; kt < KT; kt++) {
        CP_WAIT1();
        __syncthreads();

        uint32_t sA = sb + st * STAGE;
        uint32_t sB = sA + STAGE_A;

        // blocking fragment loads for ks=0 FIRST (tensor pipe needs them)...
        #pragma unroll
        for (int mt = 0; mt < 4; mt++) {
            uint32_t ad = sA + (aRow + mt * 16) * ROWB + aCol * 2;
            LDSM4(aF[0][mt][0], aF[0][mt][1], aF[0][mt][2], aF[0][mt][3], ad);
        }
        #pragma unroll
        for (int p = 0; p < 4; p++) {
            uint32_t bd = sB + (bRowBase + p * 16) * ROWB + bCol * 2;
            uint32_t r0, r1, r2, r3;
            LDSM4(r0, r1, r2, r3, bd);
            bF[0][2 * p][0] = r0; bF[0][2 * p][1] = r1;
            bF[0][2 * p + 1][0] = r2; bF[0][2 * p + 1][1] = r3;
        }

        // ...then the non-blocking cp.async burst for stage kt+2 (writes the
        // stage read at kt-1; all warps are past it — barrier above).
        if (kt + 2 < KT) {
            int st2 = st + 2; if (st2 >= NSTG) st2 -= NSTG;
            issue_stage(sb, st2, gA, gB, kt + 2, tid, K);
        }
        CP_COMMIT();                               // commit every iter (tail!)

        #pragma unroll
        for (int ks = 0; ks < 4; ks++) {           // 4 x k16 within BK=64
            int cur = ks & 1, nxt = cur ^ 1;
            if (ks < 3) {                          // prefetch ks+1 fragments
                int kc = (ks + 1) * 16;
                #pragma unroll
                for (int mt = 0; mt < 4; mt++) {
                    uint32_t ad = sA + (aRow + mt * 16) * ROWB + (aCol + kc) * 2;
                    LDSM4(aF[nxt][mt][0], aF[nxt][mt][1], aF[nxt][mt][2], aF[nxt][mt][3], ad);
                }
                #pragma unroll
                for (int p = 0; p < 4; p++) {
                    uint32_t bd = sB + (bRowBase + p * 16) * ROWB + (bCol + kc) * 2;
                    uint32_t r0, r1, r2, r3;
                    LDSM4(r0, r1, r2, r3, bd);
                    bF[nxt][2 * p][0] = r0; bF[nxt][2 * p][1] = r1;
                    bF[nxt][2 * p + 1][0] = r2; bF[nxt][2 * p + 1][1] = r3;
                }
            }
            #pragma unroll
            for (int mt = 0; mt < 4; mt++)
                #pragma unroll
                for (int nt = 0; nt < 8; nt++)
                    mma16816(acc[mt][nt], aF[cur][mt], bF[cur][nt]);
        }

        if (++st == NSTG) st = 0;
    }

    // ---------------- epilogue: fp32 stores (streaming) + bias ------------
    int rbase = mtile * BM + warpM * 64 + (L >> 2);
    int cbase = ntile * BN + warpN * 64 + (L & 3) * 2;

    float2 bv[8];
    #pragma unroll
    for (int nt = 0; nt < 8; nt++)
        bv[nt] = *(const float2*)(bias + cbase + nt * 8);

    #pragma unroll
    for (int mt = 0; mt < 4; mt++) {
        int r0 = rbase + mt * 16;
        #pragma unroll
        for (int nt = 0; nt < 8; nt++) {
            int c = cbase + nt * 8;
            float2 v0 = { acc[mt][nt][0] + bv[nt].x, acc[mt][nt][1] + bv[nt].y };
            float2 v1 = { acc[mt][nt][2] + bv[nt].x, acc[mt][nt][3] + bv[nt].y };
            __stcs((float2*)(out + (size_t)r0 * N + c), v0);
            __stcs((float2*)(out + (size_t)(r0 + 8) * N + c), v1);
        }
    }
}

// ---------------------------------------------------------------- host -----
extern "C" void kernel_launch(void* const* d_in, const int* in_sizes, int n_in,
                              void* d_out, int out_size)
{
    const float* x    = (const float*)d_in[0];
    const float* w    = (const float*)d_in[1];
    const float* bias = (const float*)d_in[2];
    float* out = (float*)d_out;

    int N  = in_sizes[2];
    int K  = in_sizes[1] / N;
    int M  = in_sizes[0] / K;
    int nw = in_sizes[1];
    int nx = in_sizes[0];

    // Order: gemm stays 4th kernel -> lands in the ncu capture slot.
    xconv_kernel<<<4096, 256>>>(x, nx / 4);
    stats1_kernel<<<1024, 256>>>(w, nw);
    binarize_kernel<<<2048, 256>>>(w, nw / 4, nw);

    void *pXh = nullptr, *pWb = nullptr;
    cudaGetSymbolAddress(&pXh, g_Xh);
    cudaGetSymbolAddress(&pWb, g_Wb);

    cudaFuncSetAttribute(gemm_kernel, cudaFuncAttributeMaxDynamicSharedMemorySize, GEMM_SMEM);

    int grid = (M / BM) * (N / BN);
    gemm_kernel<<<grid, 128, GEMM_SMEM>>>(out, bias, (const __half*)pXh,
                                          (const __half*)pWb, M, N, K);
}

// round 14
// speedup vs baseline: 1.1587x; 1.1587x over previous
#include <cuda_runtime.h>
#include <cuda_fp16.h>
#include <cstdint>

// ============================================================================
// out[M,N] = x[M,K] @ w_bin[N,K]^T + bias[N]
//   w_bin = (w < mean-std || w > mean+std) ? w : sign(w)   (std: ddof=1)
// Shapes: M=16384, K=4096, N=4096 fp32.
// Engine: fp16 convert + mma.sync.m16n8k16 pipelined GEMM (base sm_103 ISA).
// R13: cross-kt fragment pipelining — barrier moved to mid-kt (between MMA
//      bursts); next-kt ks0 fragments load under the ks1 MMA shadow, so no
//      LDSM burst is ever serial. BK=32, 5-stage, WAITG(2) => stage kt+1
//      resident at mid-kt. 128 thr, 64x64 warps, 2 CTAs/SM.
// ============================================================================

#define MAXM 16384
#define MAXN 4096
#define MAXK 4096

__device__ __half g_Xh[(size_t)MAXM * MAXK];   // 128 MiB scratch
__device__ __half g_Wb[(size_t)MAXN * MAXK];   // 32 MiB scratch
__device__ double g_part[2048];

// ---------------------------------------------------------------- stats ----
__global__ void stats1_kernel(const float* __restrict__ w, int n) {
    __shared__ double ss[256], sq[256];
    double s = 0.0, q = 0.0;
    for (int i = blockIdx.x * blockDim.x + threadIdx.x; i < n; i += gridDim.x * blockDim.x) {
        double v = (double)w[i];
        s += v; q += v * v;
    }
    ss[threadIdx.x] = s; sq[threadIdx.x] = q;
    __syncthreads();
    for (int o = 128; o > 0; o >>= 1) {
        if (threadIdx.x < o) { ss[threadIdx.x] += ss[threadIdx.x + o]; sq[threadIdx.x] += sq[threadIdx.x + o]; }
        __syncthreads();
    }
    if (threadIdx.x == 0) { g_part[blockIdx.x * 2] = ss[0]; g_part[blockIdx.x * 2 + 1] = sq[0]; }
}

__device__ __forceinline__ float binv(float w, float lo, float hi) {
    if (w < lo || w > hi) return w;
    return (w > 0.f) ? 1.f : ((w < 0.f) ? -1.f : 0.f);
}

// binarize + final threshold reduce fused (each block redundantly reduces the
// 1024 partials — deterministic, a few us total).
__global__ void binarize_kernel(const float* __restrict__ w, int n4, int n) {
    __shared__ double ss[256], sq[256];
    __shared__ float thr[2];
    double s = 0.0, q = 0.0;
    for (int i = threadIdx.x; i < 1024; i += 256) { s += g_part[2 * i]; q += g_part[2 * i + 1]; }
    ss[threadIdx.x] = s; sq[threadIdx.x] = q;
    __syncthreads();
    for (int o = 128; o > 0; o >>= 1) {
        if (threadIdx.x < o) { ss[threadIdx.x] += ss[threadIdx.x + o]; sq[threadIdx.x] += sq[threadIdx.x + o]; }
        __syncthreads();
    }
    if (threadIdx.x == 0) {
        double mean = ss[0] / (double)n;
        double var  = (sq[0] - ss[0] * ss[0] / (double)n) / (double)(n - 1);
        double sd = sqrt(var);
        thr[0] = (float)(mean - sd);
        thr[1] = (float)(mean + sd);
    }
    __syncthreads();
    float lo = thr[0], hi = thr[1];
    const float4* w4 = (const float4*)w;
    __half2* o2 = (__half2*)g_Wb;
    for (int i = blockIdx.x * blockDim.x + threadIdx.x; i < n4; i += gridDim.x * blockDim.x) {
        float4 v = w4[i];
        o2[2 * i]     = __floats2half2_rn(binv(v.x, lo, hi), binv(v.y, lo, hi));
        o2[2 * i + 1] = __floats2half2_rn(binv(v.z, lo, hi), binv(v.w, lo, hi));
    }
}

__global__ void xconv_kernel(const float* __restrict__ x, int n4) {
    const float4* x4 = (const float4*)x;
    __half2* o2 = (__half2*)g_Xh;
    for (int i = blockIdx.x * blockDim.x + threadIdx.x; i < n4; i += gridDim.x * blockDim.x) {
        float4 v = x4[i];
        o2[2 * i]     = __floats2half2_rn(v.x, v.y);
        o2[2 * i + 1] = __floats2half2_rn(v.z, v.w);
    }
}

// ---------------------------------------------------------------- GEMM -----
// CTA tile 128x128, BK=32, 5-stage cp.async, 128 threads (4 warps 2x2),
// warp tile 64x64, cross-kt fragment pipelining, 2 CTAs/SM.
// Smem rows 80B (32 fp16 + 16 pad): 16B-aligned, ldmatrix conflict-free.

#define BM 128
#define BN 128
#define BK 32
#define ROWB 80
#define STAGE_A (BM * ROWB)           // 10240
#define STAGE_B (BN * ROWB)           // 10240
#define STAGE   (STAGE_A + STAGE_B)   // 20480
#define NSTG 5
#define GEMM_SMEM (NSTG * STAGE)      // 102400 (x2 CTAs = 200KB/SM)

__device__ __forceinline__ uint32_t smem_u32(const void* p) {
    uint32_t a;
    asm("{ .reg .u64 t; cvta.to.shared.u64 t, %1; cvt.u32.u64 %0, t; }" : "=r"(a) : "l"(p));
    return a;
}
__device__ __forceinline__ void cp16(uint32_t s, const void* g) {
    asm volatile("cp.async.cg.shared.global [%0], [%1], 16;" :: "r"(s), "l"(g));
}
#define CP_COMMIT() asm volatile("cp.async.commit_group;" ::: "memory")
#define CP_WAITG(n) asm volatile("cp.async.wait_group %0;" :: "n"(n) : "memory")

#define LDSM4(r0, r1, r2, r3, addr) \
    asm volatile("ldmatrix.sync.aligned.m8n8.x4.shared.b16 {%0,%1,%2,%3}, [%4];" \
        : "=r"(r0), "=r"(r1), "=r"(r2), "=r"(r3) : "r"(addr))

__device__ __forceinline__ void mma16816(float* d, const uint32_t* a, const uint32_t* b) {
    asm volatile(
        "mma.sync.aligned.m16n8k16.row.col.f32.f16.f16.f32 "
        "{%0,%1,%2,%3}, {%4,%5,%6,%7}, {%8,%9}, {%0,%1,%2,%3};"
        : "+f"(d[0]), "+f"(d[1]), "+f"(d[2]), "+f"(d[3])
        : "r"(a[0]), "r"(a[1]), "r"(a[2]), "r"(a[3]), "r"(b[0]), "r"(b[1]));
}

// One BK=32 stage: A 128x32 fp16 (512 x 16B chunks), B 128x32 (512 chunks).
__device__ __forceinline__ void issue_stage(
    uint32_t sb, int stage, const __half* __restrict__ gA,
    const __half* __restrict__ gB, int kt, int tid, int K)
{
    uint32_t sA = sb + stage * STAGE;
    uint32_t sB = sA + STAGE_A;
    const __half* ga = gA + (size_t)kt * BK;
    #pragma unroll
    for (int j = 0; j < 4; j++) {                  // A: 512 chunks / 128 thr
        int cid = tid + j * 128;
        int r = cid >> 2, c = cid & 3;
        cp16(sA + r * ROWB + c * 16, ga + (size_t)r * K + c * 8);
    }
    const __half* gb = gB + (size_t)kt * BK;
    #pragma unroll
    for (int j = 0; j < 4; j++) {                  // B: 512 chunks / 128 thr
        int cid = tid + j * 128;
        int r = cid >> 2, c = cid & 3;
        cp16(sB + r * ROWB + c * 16, gb + (size_t)r * K + c * 8);
    }
}

__global__ void __launch_bounds__(128, 2)
gemm_kernel(float* __restrict__ out, const float* __restrict__ bias,
            const __half* __restrict__ A, const __half* __restrict__ B,
            int M, int N, int K)
{
    extern __shared__ char smem[];
    uint32_t sb = smem_u32(smem);

    int tid = threadIdx.x;
    int wid = tid >> 5, L = tid & 31;
    int warpM = wid >> 1, warpN = wid & 1;         // 2(M) x 2(N)

    int NT = N / BN;                               // 32
    int ntile = blockIdx.x % NT;                   // fast N => W stays L2-hot
    int mtile = blockIdx.x / NT;

    const __half* gA = A + (size_t)(mtile * BM) * K;
    const __half* gB = B + (size_t)(ntile * BN) * K;
    int KT = K / BK;                               // 128

    float acc[4][8][4];
    #pragma unroll
    for (int i = 0; i < 4; i++)
        #pragma unroll
        for (int j = 0; j < 8; j++)
            #pragma unroll
            for (int q = 0; q < 4; q++) acc[i][j][q] = 0.f;

    // prologue: fill 3 of 5 stages
    issue_stage(sb, 0, gA, gB, 0, tid, K); CP_COMMIT();
    issue_stage(sb, 1, gA, gB, 1, tid, K); CP_COMMIT();
    issue_stage(sb, 2, gA, gB, 2, tid, K); CP_COMMIT();

    // ldmatrix lane offsets (warp 64x64 mapping validated R6/R11/R12)
    int aRow = warpM * 64 + (L & 15);              // + mt*16
    int aCol = (L >> 4) << 3;                      // + ks*16
    int jb = L >> 3;
    int bRowBase = warpN * 64 + ((jb >> 1) << 3) + (L & 7);   // + p*16
    int bCol = (jb & 1) << 3;                      // + ks*16

    // fragment buffers: [0] = ks0 of current kt, [1] = ks1 of current kt
    uint32_t aF[2][4][4], bF[2][8][2];

    // initial: stage 0 resident (WAITG(2) leaves stages 1,2 pending)
    CP_WAITG(2);
    __syncthreads();
    {   // load ks0 fragments of kt=0 from stage 0
        #pragma unroll
        for (int mt = 0; mt < 4; mt++) {
            uint32_t ad = sb + (aRow + mt * 16) * ROWB + aCol * 2;
            LDSM4(aF[0][mt][0], aF[0][mt][1], aF[0][mt][2], aF[0][mt][3], ad);
        }
        #pragma unroll
        for (int p = 0; p < 4; p++) {
            uint32_t bd = sb + STAGE_A + (bRowBase + p * 16) * ROWB + bCol * 2;
            uint32_t r0, r1, r2, r3;
            LDSM4(r0, r1, r2, r3, bd);
            bF[0][2 * p][0] = r0; bF[0][2 * p][1] = r1;
            bF[0][2 * p + 1][0] = r2; bF[0][2 * p + 1][1] = r3;
        }
    }

    int st = 0;                                    // stage of current kt
    for (int kt = 0; kt < KT; kt++) {
        uint32_t sA = sb + st * STAGE;
        uint32_t sB = sA + STAGE_A;

        // prefetch ks1 fragments (under upcoming ks0 MMA shadow)
        #pragma unroll
        for (int mt = 0; mt < 4; mt++) {
            uint32_t ad = sA + (aRow + mt * 16) * ROWB + (aCol + 16) * 2;
            LDSM4(aF[1][mt][0], aF[1][mt][1], aF[1][mt][2], aF[1][mt][3], ad);
        }
        #pragma unroll
        for (int p = 0; p < 4; p++) {
            uint32_t bd = sB + (bRowBase + p * 16) * ROWB + (bCol + 16) * 2;
            uint32_t r0, r1, r2, r3;
            LDSM4(r0, r1, r2, r3, bd);
            bF[1][2 * p][0] = r0; bF[1][2 * p][1] = r1;
            bF[1][2 * p + 1][0] = r2; bF[1][2 * p + 1][1] = r3;
        }

        // issue stage kt+3 (buffer (kt-2)%5; all warps are >= mid-kt of kt-1,
        // whose stage-(kt-2) reads finished during kt-2)
        if (kt + 3 < KT) {
            int st3 = st + 3; if (st3 >= NSTG) st3 -= NSTG;
            issue_stage(sb, st3, gA, gB, kt + 3, tid, K);
        }
        CP_COMMIT();                               // one group per kt (tail-safe)

        // MMA ks0
        #pragma unroll
        for (int mt = 0; mt < 4; mt++)
            #pragma unroll
            for (int nt = 0; nt < 8; nt++)
                mma16816(acc[mt][nt], aF[0][mt], bF[0][nt]);

        // mid-kt barrier: stage kt+1 resident after WAITG(2)
        CP_WAITG(2);
        __syncthreads();

        // prefetch ks0 fragments of kt+1 (under ks1 MMA shadow)
        if (kt + 1 < KT) {
            int st1 = st + 1; if (st1 >= NSTG) st1 -= NSTG;
            uint32_t nA = sb + st1 * STAGE;
            uint32_t nB = nA + STAGE_A;
            #pragma unroll
            for (int mt = 0; mt < 4; mt++) {
                uint32_t ad = nA + (aRow + mt * 16) * ROWB + aCol * 2;
                LDSM4(aF[0][mt][0], aF[0][mt][1], aF[0][mt][2], aF[0][mt][3], ad);
            }
            #pragma unroll
            for (int p = 0; p < 4; p++) {
                uint32_t bd = nB + (bRowBase + p * 16) * ROWB + bCol * 2;
                uint32_t r0, r1, r2, r3;
                LDSM4(r0, r1, r2, r3, bd);
                bF[0][2 * p][0] = r0; bF[0][2 * p][1] = r1;
                bF[0][2 * p + 1][0] = r2; bF[0][2 * p + 1][1] = r3;
            }
        }

        // MMA ks1
        #pragma unroll
        for (int mt = 0; mt < 4; mt++)
            #pragma unroll
            for (int nt = 0; nt < 8; nt++)
                mma16816(acc[mt][nt], aF[1][mt], bF[1][nt]);

        if (++st == NSTG) st = 0;
    }

    // ---------------- epilogue: fp32 stores (streaming) + bias ------------
    int rbase = mtile * BM + warpM * 64 + (L >> 2);
    int cbase = ntile * BN + warpN * 64 + (L & 3) * 2;

    float2 bv[8];
    #pragma unroll
    for (int nt = 0; nt < 8; nt++)
        bv[nt] = *(const float2*)(bias + cbase + nt * 8);

    #pragma unroll
    for (int mt = 0; mt < 4; mt++) {
        int r0 = rbase + mt * 16;
        #pragma unroll
        for (int nt = 0; nt < 8; nt++) {
            int c = cbase + nt * 8;
            float2 v0 = { acc[mt][nt][0] + bv[nt].x, acc[mt][nt][1] + bv[nt].y };
            float2 v1 = { acc[mt][nt][2] + bv[nt].x, acc[mt][nt][3] + bv[nt].y };
            __stcs((float2*)(out + (size_t)r0 * N + c), v0);
            __stcs((float2*)(out + (size_t)(r0 + 8) * N + c), v1);
        }
    }
}

// ---------------------------------------------------------------- host -----
extern "C" void kernel_launch(void* const* d_in, const int* in_sizes, int n_in,
                              void* d_out, int out_size)
{
    const float* x    = (const float*)d_in[0];
    const float* w    = (const float*)d_in[1];
    const float* bias = (const float*)d_in[2];
    float* out = (float*)d_out;

    int N  = in_sizes[2];
    int K  = in_sizes[1] / N;
    int M  = in_sizes[0] / K;
    int nw = in_sizes[1];
    int nx = in_sizes[0];

    // Order: gemm stays 4th kernel -> lands in the ncu capture slot.
    xconv_kernel<<<4096, 256>>>(x, nx / 4);
    stats1_kernel<<<1024, 256>>>(w, nw);
    binarize_kernel<<<2048, 256>>>(w, nw / 4, nw);

    void *pXh = nullptr, *pWb = nullptr;
    cudaGetSymbolAddress(&pXh, g_Xh);
    cudaGetSymbolAddress(&pWb, g_Wb);

    cudaFuncSetAttribute(gemm_kernel, cudaFuncAttributeMaxDynamicSharedMemorySize, GEMM_SMEM);

    int grid = (M / BM) * (N / BN);
    gemm_kernel<<<grid, 128, GEMM_SMEM>>>(out, bias, (const __half*)pXh,
                                          (const __half*)pWb, M, N, K);
}

// round 15
// speedup vs baseline: 1.2139x; 1.0476x over previous
#include <cuda_runtime.h>
#include <cuda_fp16.h>
#include <cstdint>

// ============================================================================
// out[M,N] = x[M,K] @ w_bin[N,K]^T + bias[N]
//   w_bin = (w < mean-std || w > mean+std) ? w : sign(w)   (std: ddof=1)
// Shapes: M=16384, K=4096, N=4096 fp32.
// Engine: fp16 convert + mma.sync.m16n8k16 pipelined GEMM (base sm_103 ISA).
// R15: R13's cross-kt fragment pipelining at BK=64 — one barrier/WAITG/commit
//      per 1024 MMA cyc (was per 512); cp.async split into two 8-op halves
//      between MMA bursts. 128 thr, 64x64 warps, 3-stage, 2 CTAs/SM.
// ============================================================================

#define MAXM 16384
#define MAXN 4096
#define MAXK 4096

__device__ __half g_Xh[(size_t)MAXM * MAXK];   // 128 MiB scratch
__device__ __half g_Wb[(size_t)MAXN * MAXK];   // 32 MiB scratch
__device__ double g_part[2048];

// ---------------------------------------------------------------- stats ----
__global__ void stats1_kernel(const float* __restrict__ w, int n) {
    __shared__ double ss[256], sq[256];
    double s = 0.0, q = 0.0;
    for (int i = blockIdx.x * blockDim.x + threadIdx.x; i < n; i += gridDim.x * blockDim.x) {
        double v = (double)w[i];
        s += v; q += v * v;
    }
    ss[threadIdx.x] = s; sq[threadIdx.x] = q;
    __syncthreads();
    for (int o = 128; o > 0; o >>= 1) {
        if (threadIdx.x < o) { ss[threadIdx.x] += ss[threadIdx.x + o]; sq[threadIdx.x] += sq[threadIdx.x + o]; }
        __syncthreads();
    }
    if (threadIdx.x == 0) { g_part[blockIdx.x * 2] = ss[0]; g_part[blockIdx.x * 2 + 1] = sq[0]; }
}

__device__ __forceinline__ float binv(float w, float lo, float hi) {
    if (w < lo || w > hi) return w;
    return (w > 0.f) ? 1.f : ((w < 0.f) ? -1.f : 0.f);
}

// binarize + final threshold reduce fused (each block redundantly reduces the
// 1024 partials — deterministic, a few us total).
__global__ void binarize_kernel(const float* __restrict__ w, int n4, int n) {
    __shared__ double ss[256], sq[256];
    __shared__ float thr[2];
    double s = 0.0, q = 0.0;
    for (int i = threadIdx.x; i < 1024; i += 256) { s += g_part[2 * i]; q += g_part[2 * i + 1]; }
    ss[threadIdx.x] = s; sq[threadIdx.x] = q;
    __syncthreads();
    for (int o = 128; o > 0; o >>= 1) {
        if (threadIdx.x < o) { ss[threadIdx.x] += ss[threadIdx.x + o]; sq[threadIdx.x] += sq[threadIdx.x + o]; }
        __syncthreads();
    }
    if (threadIdx.x == 0) {
        double mean = ss[0] / (double)n;
        double var  = (sq[0] - ss[0] * ss[0] / (double)n) / (double)(n - 1);
        double sd = sqrt(var);
        thr[0] = (float)(mean - sd);
        thr[1] = (float)(mean + sd);
    }
    __syncthreads();
    float lo = thr[0], hi = thr[1];
    const float4* w4 = (const float4*)w;
    __half2* o2 = (__half2*)g_Wb;
    for (int i = blockIdx.x * blockDim.x + threadIdx.x; i < n4; i += gridDim.x * blockDim.x) {
        float4 v = w4[i];
        o2[2 * i]     = __floats2half2_rn(binv(v.x, lo, hi), binv(v.y, lo, hi));
        o2[2 * i + 1] = __floats2half2_rn(binv(v.z, lo, hi), binv(v.w, lo, hi));
    }
}

__global__ void xconv_kernel(const float* __restrict__ x, int n4) {
    const float4* x4 = (const float4*)x;
    __half2* o2 = (__half2*)g_Xh;
    for (int i = blockIdx.x * blockDim.x + threadIdx.x; i < n4; i += gridDim.x * blockDim.x) {
        float4 v = x4[i];
        o2[2 * i]     = __floats2half2_rn(v.x, v.y);
        o2[2 * i + 1] = __floats2half2_rn(v.z, v.w);
    }
}

// ---------------------------------------------------------------- GEMM -----
// CTA tile 128x128, BK=64, 3-stage cp.async, 128 threads (4 warps 2x2),
// warp tile 64x64, cross-kt fragment pipelining, 2 CTAs/SM.
// Smem rows 144B: 16B-aligned cp.async dsts, ldmatrix phase-conflict-free.

#define BM 128
#define BN 128
#define BK 64
#define ROWB 144
#define STAGE_A (BM * ROWB)           // 18432
#define STAGE_B (BN * ROWB)           // 18432
#define STAGE   (STAGE_A + STAGE_B)   // 36864
#define NSTG 3
#define GEMM_SMEM (NSTG * STAGE)      // 110592 (x2 CTAs = 221KB/SM)

__device__ __forceinline__ uint32_t smem_u32(const void* p) {
    uint32_t a;
    asm("{ .reg .u64 t; cvta.to.shared.u64 t, %1; cvt.u32.u64 %0, t; }" : "=r"(a) : "l"(p));
    return a;
}
__device__ __forceinline__ void cp16(uint32_t s, const void* g) {
    asm volatile("cp.async.cg.shared.global [%0], [%1], 16;" :: "r"(s), "l"(g));
}
#define CP_COMMIT() asm volatile("cp.async.commit_group;" ::: "memory")
#define CP_WAITG(n) asm volatile("cp.async.wait_group %0;" :: "n"(n) : "memory")

#define LDSM4(r0, r1, r2, r3, addr) \
    asm volatile("ldmatrix.sync.aligned.m8n8.x4.shared.b16 {%0,%1,%2,%3}, [%4];" \
        : "=r"(r0), "=r"(r1), "=r"(r2), "=r"(r3) : "r"(addr))

__device__ __forceinline__ void mma16816(float* d, const uint32_t* a, const uint32_t* b) {
    asm volatile(
        "mma.sync.aligned.m16n8k16.row.col.f32.f16.f16.f32 "
        "{%0,%1,%2,%3}, {%4,%5,%6,%7}, {%8,%9}, {%0,%1,%2,%3};"
        : "+f"(d[0]), "+f"(d[1]), "+f"(d[2]), "+f"(d[3])
        : "r"(a[0]), "r"(a[1]), "r"(a[2]), "r"(a[3]), "r"(b[0]), "r"(b[1]));
}

// Half-stages for BK=64: A half = 512 chunks, B half = 512 chunks (128 thr).
__device__ __forceinline__ void issue_stage_A(
    uint32_t sb, int stage, const __half* __restrict__ gA, int kt, int tid, int K)
{
    uint32_t sA = sb + stage * STAGE;
    const __half* ga = gA + (size_t)kt * BK;
    #pragma unroll
    for (int j = 0; j < 8; j++) {                  // A: 1024 chunks / 128 thr
        int cid = tid + j * 128;
        int r = cid >> 3, c = cid & 7;
        cp16(sA + r * ROWB + c * 16, ga + (size_t)r * K + c * 8);
    }
}
__device__ __forceinline__ void issue_stage_B(
    uint32_t sb, int stage, const __half* __restrict__ gB, int kt, int tid, int K)
{
    uint32_t sB = sb + stage * STAGE + STAGE_A;
    const __half* gb = gB + (size_t)kt * BK;
    #pragma unroll
    for (int j = 0; j < 8; j++) {                  // B: 1024 chunks / 128 thr
        int cid = tid + j * 128;
        int r = cid >> 3, c = cid & 7;
        cp16(sB + r * ROWB + c * 16, gb + (size_t)r * K + c * 8);
    }
}

// Fragment loads for one k16 step.
#define LOAD_A_FRAGS(dst, base, kc) do { \
    _Pragma("unroll") \
    for (int mt = 0; mt < 4; mt++) { \
        uint32_t ad = (base) + (aRow + mt * 16) * ROWB + ((aCol + (kc)) * 2); \
        LDSM4((dst)[mt][0], (dst)[mt][1], (dst)[mt][2], (dst)[mt][3], ad); \
    } } while (0)

#define LOAD_B_FRAGS(dst, base, kc) do { \
    _Pragma("unroll") \
    for (int p = 0; p < 4; p++) { \
        uint32_t bd = (base) + (bRowBase + p * 16) * ROWB + ((bCol + (kc)) * 2); \
        uint32_t r0, r1, r2, r3; \
        LDSM4(r0, r1, r2, r3, bd); \
        (dst)[2 * p][0] = r0; (dst)[2 * p][1] = r1; \
        (dst)[2 * p + 1][0] = r2; (dst)[2 * p + 1][1] = r3; \
    } } while (0)

#define MMA_BURST(af, bf) do { \
    _Pragma("unroll") \
    for (int mt = 0; mt < 4; mt++) \
        _Pragma("unroll") \
        for (int nt = 0; nt < 8; nt++) \
            mma16816(acc[mt][nt], (af)[mt], (bf)[nt]); \
    } while (0)

__global__ void __launch_bounds__(128, 2)
gemm_kernel(float* __restrict__ out, const float* __restrict__ bias,
            const __half* __restrict__ A, const __half* __restrict__ B,
            int M, int N, int K)
{
    extern __shared__ char smem[];
    uint32_t sb = smem_u32(smem);

    int tid = threadIdx.x;
    int wid = tid >> 5, L = tid & 31;
    int warpM = wid >> 1, warpN = wid & 1;         // 2(M) x 2(N)

    int NT = N / BN;                               // 32
    int ntile = blockIdx.x % NT;                   // fast N => W stays L2-hot
    int mtile = blockIdx.x / NT;

    const __half* gA = A + (size_t)(mtile * BM) * K;
    const __half* gB = B + (size_t)(ntile * BN) * K;
    int KT = K / BK;                               // 64

    float acc[4][8][4];
    #pragma unroll
    for (int i = 0; i < 4; i++)
        #pragma unroll
        for (int j = 0; j < 8; j++)
            #pragma unroll
            for (int q = 0; q < 4; q++) acc[i][j][q] = 0.f;

    // prologue: fill stages 0,1
    issue_stage_A(sb, 0, gA, 0, tid, K);
    issue_stage_B(sb, 0, gB, 0, tid, K); CP_COMMIT();
    issue_stage_A(sb, 1, gA, 1, tid, K);
    issue_stage_B(sb, 1, gB, 1, tid, K); CP_COMMIT();

    // ldmatrix lane offsets (warp 64x64 mapping validated R6/R11-R14)
    int aRow = warpM * 64 + (L & 15);              // + mt*16
    int aCol = (L >> 4) << 3;                      // + ks*16
    int jb = L >> 3;
    int bRowBase = warpN * 64 + ((jb >> 1) << 3) + (L & 7);   // + p*16
    int bCol = (jb & 1) << 3;                      // + ks*16

    // F0 carries ks0 -> ks2 -> next-ks0 ; F1 carries ks1 -> ks3
    uint32_t aF[2][4][4], bF[2][8][2];

    // stage 0 resident (leave stage 1 pending), load kt0 ks0 fragments
    CP_WAITG(1);
    __syncthreads();
    LOAD_A_FRAGS(aF[0], sb, 0);
    LOAD_B_FRAGS(bF[0], sb + STAGE_A, 0);

    int st = 0;                                    // stage of current kt
    for (int kt = 0; kt < KT; kt++) {
        uint32_t sA = sb + st * STAGE;
        uint32_t sB = sA + STAGE_A;
        int st2 = st + 2; if (st2 >= NSTG) st2 -= NSTG;

        // ks1 fragments (issue overlaps prior MMA drain / upcoming ks0 burst)
        LOAD_A_FRAGS(aF[1], sA, 16);
        LOAD_B_FRAGS(bF[1], sB, 16);

        MMA_BURST(aF[0], bF[0]);                   // ks0

        if (kt + 2 < KT) issue_stage_A(sb, st2, gA, kt + 2, tid, K);

        LOAD_A_FRAGS(aF[0], sA, 32);               // ks2 fragments
        LOAD_B_FRAGS(bF[0], sB, 32);

        MMA_BURST(aF[1], bF[1]);                   // ks1

        if (kt + 2 < KT) issue_stage_B(sb, st2, gB, kt + 2, tid, K);
        CP_COMMIT();                               // one group per kt (tail-safe)

        LOAD_A_FRAGS(aF[1], sA, 48);               // ks3 fragments (last st read)
        LOAD_B_FRAGS(bF[1], sB, 48);

        MMA_BURST(aF[0], bF[0]);                   // ks2

        // single sync point per kt: stage kt+1 resident (only kt+2 pending);
        // all warps past all reads of stage st => next kt's issue is safe.
        CP_WAITG(1);
        __syncthreads();

        // cross-kt: ks0 fragments of kt+1 under the ks3 MMA shadow
        if (kt + 1 < KT) {
            int st1 = st + 1; if (st1 >= NSTG) st1 -= NSTG;
            uint32_t nA = sb + st1 * STAGE;
            LOAD_A_FRAGS(aF[0], nA, 0);
            LOAD_B_FRAGS(bF[0], nA + STAGE_A, 0);
        }

        MMA_BURST(aF[1], bF[1]);                   // ks3

        if (++st == NSTG) st = 0;
    }

    // ---------------- epilogue: fp32 stores (streaming) + bias ------------
    int rbase = mtile * BM + warpM * 64 + (L >> 2);
    int cbase = ntile * BN + warpN * 64 + (L & 3) * 2;

    float2 bv[8];
    #pragma unroll
    for (int nt = 0; nt < 8; nt++)
        bv[nt] = *(const float2*)(bias + cbase + nt * 8);

    #pragma unroll
    for (int mt = 0; mt < 4; mt++) {
        int r0 = rbase + mt * 16;
        #pragma unroll
        for (int nt = 0; nt < 8; nt++) {
            int c = cbase + nt * 8;
            float2 v0 = { acc[mt][nt][0] + bv[nt].x, acc[mt][nt][1] + bv[nt].y };
            float2 v1 = { acc[mt][nt][2] + bv[nt].x, acc[mt][nt][3] + bv[nt].y };
            __stcs((float2*)(out + (size_t)r0 * N + c), v0);
            __stcs((float2*)(out + (size_t)(r0 + 8) * N + c), v1);
        }
    }
}

// ---------------------------------------------------------------- host -----
extern "C" void kernel_launch(void* const* d_in, const int* in_sizes, int n_in,
                              void* d_out, int out_size)
{
    const float* x    = (const float*)d_in[0];
    const float* w    = (const float*)d_in[1];
    const float* bias = (const float*)d_in[2];
    float* out = (float*)d_out;

    int N  = in_sizes[2];
    int K  = in_sizes[1] / N;
    int M  = in_sizes[0] / K;
    int nw = in_sizes[1];
    int nx = in_sizes[0];

    // Order: gemm stays 4th kernel -> lands in the ncu capture slot.
    xconv_kernel<<<4096, 256>>>(x, nx / 4);
    stats1_kernel<<<1024, 256>>>(w, nw);
    binarize_kernel<<<2048, 256>>>(w, nw / 4, nw);

    void *pXh = nullptr, *pWb = nullptr;
    cudaGetSymbolAddress(&pXh, g_Xh);
    cudaGetSymbolAddress(&pWb, g_Wb);

    cudaFuncSetAttribute(gemm_kernel, cudaFuncAttributeMaxDynamicSharedMemorySize, GEMM_SMEM);

    int grid = (M / BM) * (N / BN);
    gemm_kernel<<<grid, 128, GEMM_SMEM>>>(out, bias, (const __half*)pXh,
                                          (const __half*)pWb, M, N, K);
}